// round 4
// baseline (speedup 1.0000x reference)
#include <cuda_runtime.h>
#include <cuda_bf16.h>

#define BB 8
#define NN 16384
#define NPT 512
#define KNB 32
#define CCH 128
#define FPS_T 1024
#define PAIRS 8   // 16 points per thread = 8 f32x2 pairs

// neighbor index lists (ball query -> maxpool)
__device__ int g_idx[BB * NPT * KNB];

// ---- packed f32x2 helpers (per-lane IEEE identical to scalar ops, no FMA) ----
__device__ __forceinline__ unsigned long long f2add(unsigned long long a, unsigned long long b) {
    unsigned long long r;
    asm("add.rn.f32x2 %0, %1, %2;" : "=l"(r) : "l"(a), "l"(b));
    return r;
}
__device__ __forceinline__ unsigned long long f2mul(unsigned long long a, unsigned long long b) {
    unsigned long long r;
    asm("mul.rn.f32x2 %0, %1, %2;" : "=l"(r) : "l"(a), "l"(b));
    return r;
}
__device__ __forceinline__ unsigned long long pack2(float a, float b) {
    unsigned long long r;
    unsigned ia = __float_as_uint(a), ib = __float_as_uint(b);
    asm("mov.b64 %0, {%1, %2};" : "=l"(r) : "r"(ia), "r"(ib));
    return r;
}
__device__ __forceinline__ void unpack2(unsigned long long v, float& a, float& b) {
    unsigned ia, ib;
    asm("mov.b64 {%0, %1}, %2;" : "=r"(ia), "=r"(ib) : "l"(v));
    a = __uint_as_float(ia);
    b = __uint_as_float(ib);
}

// =====================================================================
// Kernel 1: farthest point sampling. One block per batch, persistent.
// d = ((dx*dx + dy*dy) + dz*dz), no FMA. Argmax first-index tie-break.
// =====================================================================
__global__ __launch_bounds__(FPS_T, 1) void fps_kernel(const float* __restrict__ xyz,
                                                       float* __restrict__ out_newxyz) {
    extern __shared__ unsigned long long smemu[];
    unsigned long long* sX = smemu;           // 8192 pairs
    unsigned long long* sY = sX + 8192;
    unsigned long long* sZ = sY + 8192;
    unsigned long long* sKeys = sZ + 8192;    // 32
    int* sB = (int*)(sKeys + 32);

    const int b = blockIdx.x;
    const int t = threadIdx.x;
    const float* xb = xyz + (size_t)b * NN * 3;

    // point n: i = n>>10 in [0,16), tt = n&1023; pair slot j=i>>1, half h=i&1.
    for (int n = t; n < NN; n += FPS_T) {
        float x = xb[n * 3 + 0], y = xb[n * 3 + 1], z = xb[n * 3 + 2];
        int i = n >> 10, tt = n & 1023, j = i >> 1, h = i & 1;
        ((float*)&sX[j * 1024 + tt])[h] = x;
        ((float*)&sY[j * 1024 + tt])[h] = y;
        ((float*)&sZ[j * 1024 + tt])[h] = z;
    }
    float M[2 * PAIRS];
#pragma unroll
    for (int i = 0; i < 2 * PAIRS; i++) M[i] = 1e10f;
    __syncthreads();

    // centroid 0 = point 0 (reference init_far = 0)
    float cx = ((float*)&sX[t < 1 ? 0 : 0])[0];  // slot 0 half 0 = point 0... broadcast below
    cx = ((float*)&sX[0])[0];
    float cy = ((float*)&sY[0])[0];
    float cz = ((float*)&sZ[0])[0];
    float* ob = out_newxyz + (size_t)b * NPT * 3;
    if (t == 0) { ob[0] = cx; ob[1] = cy; ob[2] = cz; }

    for (int it = 1; it < NPT; it++) {
        unsigned long long ncx = pack2(-cx, -cx);
        unsigned long long ncy = pack2(-cy, -cy);
        unsigned long long ncz = pack2(-cz, -cz);
#pragma unroll
        for (int j = 0; j < PAIRS; j++) {
            unsigned long long xv = sX[j * 1024 + t];
            unsigned long long yv = sY[j * 1024 + t];
            unsigned long long zv = sZ[j * 1024 + t];
            unsigned long long dx = f2add(xv, ncx);   // x + (-cx) == x - cx exactly
            unsigned long long dy = f2add(yv, ncy);
            unsigned long long dz = f2add(zv, ncz);
            unsigned long long s =
                f2add(f2add(f2mul(dx, dx), f2mul(dy, dy)), f2mul(dz, dz));
            float d0, d1;
            unpack2(s, d0, d1);
            M[2 * j] = fminf(M[2 * j], d0);
            M[2 * j + 1] = fminf(M[2 * j + 1], d1);
        }
        // thread-local argmax; M index i maps to point n = i*1024 + t, ascending
        float bv = M[0];
        int bi = 0;
#pragma unroll
        for (int i = 1; i < 2 * PAIRS; i++)
            if (M[i] > bv) { bv = M[i]; bi = i; }
        unsigned gidx = (unsigned)((bi << 10) | t);
        unsigned long long key =
            ((unsigned long long)__float_as_uint(bv) << 32) | (unsigned)(~gidx);
#pragma unroll
        for (int o = 16; o > 0; o >>= 1) {
            unsigned long long other = __shfl_down_sync(0xffffffffu, key, o);
            if (other > key) key = other;
        }
        int w = t >> 5;
        if ((t & 31) == 0) sKeys[w] = key;
        __syncthreads();
        if (w == 0) {
            key = sKeys[t & 31];
#pragma unroll
            for (int o = 16; o > 0; o >>= 1) {
                unsigned long long other = __shfl_down_sync(0xffffffffu, key, o);
                if (other > key) key = other;
            }
            if (t == 0) *sB = (int)(~((unsigned)key));
        }
        __syncthreads();
        int g = *sB;
        int i2 = g >> 10, t2 = g & 1023, j2 = i2 >> 1, h2 = i2 & 1;
        cx = ((float*)&sX[j2 * 1024 + t2])[h2];
        cy = ((float*)&sY[j2 * 1024 + t2])[h2];
        cz = ((float*)&sZ[j2 * 1024 + t2])[h2];
        if (t == 0) { ob[it * 3 + 0] = cx; ob[it * 3 + 1] = cy; ob[it * 3 + 2] = cz; }
    }
}

// =====================================================================
// Kernel 2: ball query. One warp per centroid, ordered first-32 within
// radius via ballot + prefix popc, early exit. Expanded distance:
// sq = ((-2*dot + |s|^2) + |n|^2), plain mul/add (no FMA).
// =====================================================================
__global__ __launch_bounds__(256) void ballq_kernel(const float* __restrict__ xyz,
                                                    const float* __restrict__ newxyz) {
    const int b = blockIdx.y;
    const int s = blockIdx.x * 8 + (threadIdx.x >> 5);
    const int lane = threadIdx.x & 31;
    const float* xb = xyz + (size_t)b * NN * 3;
    const float* c = newxyz + ((size_t)b * NPT + s) * 3;
    const float cx = c[0], cy = c[1], cz = c[2];
    const float sqs = __fadd_rn(__fadd_rn(__fmul_rn(cx, cx), __fmul_rn(cy, cy)),
                                __fmul_rn(cz, cz));
    int* out = g_idx + ((size_t)b * NPT + s) * KNB;
    int have = 0;
    int first = 0;

    for (int n0 = 0; n0 < NN && have < KNB; n0 += 32) {
        int n = n0 + lane;
        float x = xb[3 * n + 0], y = xb[3 * n + 1], z = xb[3 * n + 2];
        float sqn = __fadd_rn(__fadd_rn(__fmul_rn(x, x), __fmul_rn(y, y)),
                              __fmul_rn(z, z));
        float dot = __fadd_rn(__fadd_rn(__fmul_rn(cx, x), __fmul_rn(cy, y)),
                              __fmul_rn(cz, z));
        float sq = __fadd_rn(__fadd_rn(__fmul_rn(-2.0f, dot), sqs), sqn);
        bool inb = !(sq > 0.04f);
        unsigned m = __ballot_sync(0xffffffffu, inb);
        if (m) {
            if (have == 0) first = n0 + __ffs(m) - 1;
            if (inb) {
                int pos = have + __popc(m & ((1u << lane) - 1u));
                if (pos < KNB) out[pos] = n;
            }
            have += __popc(m);
        }
    }
    if (have > KNB) have = KNB;
    for (int k = have + lane; k < KNB; k += 32) out[k] = first;
}

// =====================================================================
// Kernel 3: grouped feature max-pool. Block per (b,s), thread = channel.
// =====================================================================
__global__ __launch_bounds__(CCH) void maxpool_kernel(const float* __restrict__ feat,
                                                      float* __restrict__ out_sub) {
    __shared__ int sidx[KNB];
    const int b = blockIdx.y, s = blockIdx.x, cch = threadIdx.x;
    if (cch < KNB) sidx[cch] = g_idx[((size_t)b * NPT + s) * KNB + cch];
    __syncthreads();
    const float* f = feat + ((size_t)b * CCH + cch) * NN;
    float m = -3.402823466e38f;
#pragma unroll
    for (int k = 0; k < KNB; k++) m = fmaxf(m, __ldg(f + sidx[k]));
    out_sub[((size_t)b * CCH + cch) * NPT + s] = m;
}

extern "C" void kernel_launch(void* const* d_in, const int* in_sizes, int n_in,
                              void* d_out, int out_size) {
    const float* xyz = (const float*)d_in[0];       // (8,16384,3)
    const float* feat = (const float*)d_in[1];      // (8,128,16384)
    float* out = (float*)d_out;
    float* out_newxyz = out;                         // (8,512,3)
    float* out_sub = out + (size_t)BB * NPT * 3;     // (8,128,512)

    static int smem_set = 0;
    const int smem = (8192 * 3 + 32) * 8 + 16;
    if (!smem_set) {
        cudaFuncSetAttribute(fps_kernel, cudaFuncAttributeMaxDynamicSharedMemorySize, smem);
        smem_set = 1;
    }

    fps_kernel<<<BB, FPS_T, smem>>>(xyz, out_newxyz);
    ballq_kernel<<<dim3(NPT / 8, BB), 256>>>(xyz, out_newxyz);
    maxpool_kernel<<<dim3(NPT, BB), CCH>>>(feat, out_sub);
}

// round 5
// speedup vs baseline: 1.1831x; 1.1831x over previous
#include <cuda_runtime.h>
#include <cuda_bf16.h>
#include <float.h>

#define BB 8
#define NN 16384
#define NPT 512
#define KNB 32
#define CCH 128
#define FPS_T 1024
#define PPT 16    // points per thread
#define PAIRS 8   // 8 f32x2 pairs per thread

// scratch: neighbor lists + transposed features
__device__ int g_idx[BB * NPT * KNB];
__device__ float g_ft[(size_t)BB * NN * CCH];   // (b, n, c)

// ---- packed f32x2 helpers (per-lane IEEE identical to scalar, no FMA) ----
__device__ __forceinline__ unsigned long long f2add(unsigned long long a, unsigned long long b) {
    unsigned long long r;
    asm("add.rn.f32x2 %0, %1, %2;" : "=l"(r) : "l"(a), "l"(b));
    return r;
}
__device__ __forceinline__ unsigned long long f2mul(unsigned long long a, unsigned long long b) {
    unsigned long long r;
    asm("mul.rn.f32x2 %0, %1, %2;" : "=l"(r) : "l"(a), "l"(b));
    return r;
}
__device__ __forceinline__ unsigned long long pack2(float a, float b) {
    unsigned long long r;
    unsigned ia = __float_as_uint(a), ib = __float_as_uint(b);
    asm("mov.b64 %0, {%1, %2};" : "=l"(r) : "r"(ia), "r"(ib));
    return r;
}
__device__ __forceinline__ void unpack2(unsigned long long v, float& a, float& b) {
    unsigned ia, ib;
    asm("mov.b64 {%0, %1}, %2;" : "=r"(ia), "=r"(ib) : "l"(v));
    a = __uint_as_float(ia);
    b = __uint_as_float(ib);
}

__device__ __forceinline__ unsigned spread5(unsigned x) {
    x &= 0x3ffu;
    x = (x | (x << 16)) & 0x030000FFu;
    x = (x | (x << 8))  & 0x0300F00Fu;
    x = (x | (x << 4))  & 0x030C30C3u;
    x = (x | (x << 2))  & 0x09249249u;
    return x;
}

// =====================================================================
// Kernel 1: FPS with exact geometric pruning.
// Points Morton-sorted; thread t owns sorted positions [16t, 16t+16) with
// a register bbox. Skip chunk update iff dmin2(bbox,c)*0.999 >= chunk max
// (provably a no-op on the exact min-distance array -> bit-exact).
// d = ((dx*dx + dy*dy) + dz*dz) via f32x2, no FMA. Tie-break: smallest
// ORIGINAL index (key = distBits<<32 | ~origIdx).
// =====================================================================
__global__ __launch_bounds__(FPS_T, 1) void fps_kernel(const float* __restrict__ xyz,
                                                       float* __restrict__ out_newxyz) {
    extern __shared__ unsigned long long smemu[];
    unsigned long long* sX = smemu;           // 8192 pairs (sorted order, [k/2][t] layout)
    unsigned long long* sY = sX + 8192;
    unsigned long long* sZ = sY + 8192;
    unsigned long long* sWK = sZ + 8192;      // 32 warps x {key, xbits, ybits, zbits}
    float* sC = (float*)(sWK + 128);          // broadcast centroid
    unsigned* skey = (unsigned*)sX;           // sort scratch (overlaps sX, used first)

    const int b = blockIdx.x, t = threadIdx.x;
    const float* xb = xyz + (size_t)b * NN * 3;
    float* ob = out_newxyz + (size_t)b * NPT * 3;

    // ---- build Morton keys ----
    for (int n = t; n < NN; n += FPS_T) {
        float x = xb[3 * n], y = xb[3 * n + 1], z = xb[3 * n + 2];
        unsigned mx = (unsigned)min(31, (int)(x * 32.0f));
        unsigned my = (unsigned)min(31, (int)(y * 32.0f));
        unsigned mz = (unsigned)min(31, (int)(z * 32.0f));
        unsigned m = spread5(mx) | (spread5(my) << 1) | (spread5(mz) << 2);
        skey[n] = (m << 14) | (unsigned)n;
    }
    __syncthreads();

    // ---- bitonic sort (perf-only: pruning is correct for any order) ----
    for (unsigned k = 2; k <= NN; k <<= 1) {
        for (unsigned j = k >> 1; j > 0; j >>= 1) {
            for (int i = t; i < NN; i += FPS_T) {
                int ixj = i ^ (int)j;
                if (ixj > i) {
                    unsigned a = skey[i], c2 = skey[ixj];
                    bool up = ((i & (int)k) == 0);
                    if ((a > c2) == up) { skey[i] = c2; skey[ixj] = a; }
                }
            }
            __syncthreads();
        }
    }

    // ---- grab my 16 sorted original indices ----
    unsigned myi[PPT];
#pragma unroll
    for (int k = 0; k < PPT; k++) myi[k] = skey[t * PPT + k] & 16383u;
    __syncthreads();  // done reading skey before overwriting sX

    // ---- load coords (sorted, transposed layout), bbox, locate point 0 ----
    float lox = FLT_MAX, loy = FLT_MAX, loz = FLT_MAX;
    float hix = -FLT_MAX, hiy = -FLT_MAX, hiz = -FLT_MAX;
#pragma unroll
    for (int k = 0; k < PPT; k++) {
        unsigned n = myi[k];
        float x = xb[3 * n], y = xb[3 * n + 1], z = xb[3 * n + 2];
        int j = k >> 1, h = k & 1;
        ((float*)&sX[j * 1024 + t])[h] = x;
        ((float*)&sY[j * 1024 + t])[h] = y;
        ((float*)&sZ[j * 1024 + t])[h] = z;
        lox = fminf(lox, x); hix = fmaxf(hix, x);
        loy = fminf(loy, y); hiy = fmaxf(hiy, y);
        loz = fminf(loz, z); hiz = fmaxf(hiz, z);
        if (n == 0u) {  // centroid 0 = original point 0 (reference init_far = 0)
            sC[0] = x; sC[1] = y; sC[2] = z;
            ob[0] = x; ob[1] = y; ob[2] = z;
        }
    }
    unsigned pidx[PAIRS];
#pragma unroll
    for (int j = 0; j < PAIRS; j++) pidx[j] = myi[2 * j] | (myi[2 * j + 1] << 16);

    float M[PPT];
#pragma unroll
    for (int k = 0; k < PPT; k++) M[k] = 1e10f;
    float localmax = 1e10f;
    unsigned long long key = 0;
    int argk = 0;
    __syncthreads();

    float cx = sC[0], cy = sC[1], cz = sC[2];
    const int w = t >> 5;

    for (int it = 1; it < NPT; it++) {
        // conservative chunk prune (0.999 slack >> fp rounding -> never unsafe)
        float dxv = fmaxf(0.0f, fmaxf(lox - cx, cx - hix));
        float dyv = fmaxf(0.0f, fmaxf(loy - cy, cy - hiy));
        float dzv = fmaxf(0.0f, fmaxf(loz - cz, cz - hiz));
        float dmin2 = (dxv * dxv + dyv * dyv + dzv * dzv) * 0.999f;
        bool upd = dmin2 < localmax;
        if (upd) {
            unsigned long long ncx = pack2(-cx, -cx);
            unsigned long long ncy = pack2(-cy, -cy);
            unsigned long long ncz = pack2(-cz, -cz);
#pragma unroll
            for (int j = 0; j < PAIRS; j++) {
                unsigned long long xv = sX[j * 1024 + t];
                unsigned long long yv = sY[j * 1024 + t];
                unsigned long long zv = sZ[j * 1024 + t];
                unsigned long long dx = f2add(xv, ncx);  // x + (-cx) == x - cx exactly
                unsigned long long dy = f2add(yv, ncy);
                unsigned long long dz = f2add(zv, ncz);
                unsigned long long s =
                    f2add(f2add(f2mul(dx, dx), f2mul(dy, dy)), f2mul(dz, dz));
                float d0, d1;
                unpack2(s, d0, d1);
                M[2 * j] = fminf(M[2 * j], d0);
                M[2 * j + 1] = fminf(M[2 * j + 1], d1);
            }
            unsigned long long best = 0;
            int bk = 0;
#pragma unroll
            for (int k = 0; k < PPT; k++) {
                unsigned o = (pidx[k >> 1] >> ((k & 1) * 16)) & 0xFFFFu;
                unsigned long long kk =
                    ((unsigned long long)__float_as_uint(M[k]) << 32) | (unsigned)(~o);
                if (kk > best) { best = kk; bk = k; }
            }
            key = best; argk = bk;
            localmax = __uint_as_float((unsigned)(best >> 32));
        }
        unsigned anyu = __ballot_sync(0xffffffffu, upd);
        if (anyu) {  // only warps whose chunk max may have changed re-reduce
            unsigned long long wk = key;
#pragma unroll
            for (int o = 16; o > 0; o >>= 1) {
                unsigned long long v = __shfl_xor_sync(0xffffffffu, wk, o);
                if (v > wk) wk = v;
            }
            if (wk == key) {  // unique owner (key embeds unique orig idx)
                int j = argk >> 1, h = argk & 1;
                float px = ((float*)&sX[j * 1024 + t])[h];
                float py = ((float*)&sY[j * 1024 + t])[h];
                float pz = ((float*)&sZ[j * 1024 + t])[h];
                sWK[4 * w] = key;
                sWK[4 * w + 1] = (unsigned long long)__float_as_uint(px);
                sWK[4 * w + 2] = (unsigned long long)__float_as_uint(py);
                sWK[4 * w + 3] = (unsigned long long)__float_as_uint(pz);
            }
        }
        __syncthreads();
        if (t < 32) {  // warp 0: reduce 32 cached warp keys, publish centroid coords
            unsigned long long kj = sWK[4 * t];
            unsigned long long mx2 = kj;
#pragma unroll
            for (int o = 16; o > 0; o >>= 1) {
                unsigned long long v = __shfl_xor_sync(0xffffffffu, mx2, o);
                if (v > mx2) mx2 = v;
            }
            if (mx2 == kj) {
                float px = __uint_as_float((unsigned)sWK[4 * t + 1]);
                float py = __uint_as_float((unsigned)sWK[4 * t + 2]);
                float pz = __uint_as_float((unsigned)sWK[4 * t + 3]);
                sC[0] = px; sC[1] = py; sC[2] = pz;
                ob[3 * it] = px; ob[3 * it + 1] = py; ob[3 * it + 2] = pz;
            }
        }
        __syncthreads();
        cx = sC[0]; cy = sC[1]; cz = sC[2];
    }
}

// =====================================================================
// Kernel 2: ball query (unchanged from passing round). One warp per
// centroid, ordered first-32 in radius via ballot + prefix popc.
// =====================================================================
__global__ __launch_bounds__(256) void ballq_kernel(const float* __restrict__ xyz,
                                                    const float* __restrict__ newxyz) {
    const int b = blockIdx.y;
    const int s = blockIdx.x * 8 + (threadIdx.x >> 5);
    const int lane = threadIdx.x & 31;
    const float* xb = xyz + (size_t)b * NN * 3;
    const float* c = newxyz + ((size_t)b * NPT + s) * 3;
    const float cx = c[0], cy = c[1], cz = c[2];
    const float sqs = __fadd_rn(__fadd_rn(__fmul_rn(cx, cx), __fmul_rn(cy, cy)),
                                __fmul_rn(cz, cz));
    int* out = g_idx + ((size_t)b * NPT + s) * KNB;
    int have = 0;
    int first = 0;

    for (int n0 = 0; n0 < NN && have < KNB; n0 += 32) {
        int n = n0 + lane;
        float x = xb[3 * n + 0], y = xb[3 * n + 1], z = xb[3 * n + 2];
        float sqn = __fadd_rn(__fadd_rn(__fmul_rn(x, x), __fmul_rn(y, y)),
                              __fmul_rn(z, z));
        float dot = __fadd_rn(__fadd_rn(__fmul_rn(cx, x), __fmul_rn(cy, y)),
                              __fmul_rn(cz, z));
        float sq = __fadd_rn(__fadd_rn(__fmul_rn(-2.0f, dot), sqs), sqn);
        bool inb = !(sq > 0.04f);
        unsigned m = __ballot_sync(0xffffffffu, inb);
        if (m) {
            if (have == 0) first = n0 + __ffs(m) - 1;
            if (inb) {
                int pos = have + __popc(m & ((1u << lane) - 1u));
                if (pos < KNB) out[pos] = n;
            }
            have += __popc(m);
        }
    }
    if (have > KNB) have = KNB;
    for (int k = have + lane; k < KNB; k += 32) out[k] = first;
}

// =====================================================================
// Kernel 3a: feature transpose (b,c,n) -> (b,n,c) so maxpool gathers
// become 512B coalesced rows.
// =====================================================================
__global__ __launch_bounds__(256) void transpose_kernel(const float* __restrict__ feat) {
    __shared__ float tile[32][33];
    const int b = blockIdx.z;
    const int n0 = blockIdx.x * 32, c0 = blockIdx.y * 32;
    const int tx = threadIdx.x, ty = threadIdx.y;  // block (32,8)
    const float* src = feat + (size_t)b * CCH * NN;
#pragma unroll
    for (int r = 0; r < 4; r++)
        tile[ty + 8 * r][tx] = src[(size_t)(c0 + ty + 8 * r) * NN + n0 + tx];
    __syncthreads();
    float* dst = g_ft + (size_t)b * NN * CCH;
#pragma unroll
    for (int r = 0; r < 4; r++)
        dst[(size_t)(n0 + ty + 8 * r) * CCH + c0 + tx] = tile[tx][ty + 8 * r];
}

// =====================================================================
// Kernel 3b: grouped max-pool. Block = (b, 32 centroids); thread = channel.
// Coalesced 512B gather rows from g_ft; results staged in SMEM for
// coalesced output stores.
// =====================================================================
__global__ __launch_bounds__(CCH) void maxpool_kernel(float* __restrict__ out_sub) {
    __shared__ int sidx[32 * KNB];
    __shared__ float tile[CCH * 33];
    const int b = blockIdx.y, s0 = blockIdx.x * 32;
    const int cch = threadIdx.x;
    for (int i = cch; i < 32 * KNB; i += CCH)
        sidx[i] = g_idx[((size_t)b * NPT + s0) * KNB + i];
    __syncthreads();
    const float* fb = g_ft + (size_t)b * NN * CCH;
    for (int sl = 0; sl < 32; sl++) {
        float m = -FLT_MAX;
#pragma unroll
        for (int k = 0; k < KNB; k++)
            m = fmaxf(m, fb[(size_t)sidx[sl * KNB + k] * CCH + cch]);
        tile[cch * 33 + sl] = m;
    }
    __syncthreads();
    for (int i = cch; i < CCH * 32; i += CCH) {
        int cp = i >> 5, j = i & 31;
        out_sub[((size_t)b * CCH + cp) * NPT + s0 + j] = tile[cp * 33 + j];
    }
}

extern "C" void kernel_launch(void* const* d_in, const int* in_sizes, int n_in,
                              void* d_out, int out_size) {
    const float* xyz = (const float*)d_in[0];    // (8,16384,3)
    const float* feat = (const float*)d_in[1];   // (8,128,16384)
    float* out = (float*)d_out;
    float* out_newxyz = out;                      // (8,512,3)
    float* out_sub = out + (size_t)BB * NPT * 3;  // (8,128,512)

    static int smem_set = 0;
    const int smem = (8192 * 3 + 128) * 8 + 16;   // 197,648 B
    if (!smem_set) {
        cudaFuncSetAttribute(fps_kernel, cudaFuncAttributeMaxDynamicSharedMemorySize, smem);
        smem_set = 1;
    }

    transpose_kernel<<<dim3(NN / 32, CCH / 32, BB), dim3(32, 8)>>>(feat);
    fps_kernel<<<BB, FPS_T, smem>>>(xyz, out_newxyz);
    ballq_kernel<<<dim3(NPT / 8, BB), 256>>>(xyz, out_newxyz);
    maxpool_kernel<<<dim3(NPT / 32, BB), CCH>>>(out_sub);
}